// round 4
// baseline (speedup 1.0000x reference)
#include <cuda_runtime.h>
#include <cuda_bf16.h>
#include <cstdint>

#define BT 48
#define NN 1024
#define FF 64

// ---------------------------------------------------------------- helpers
__device__ __forceinline__ uint32_t smem_to_u32(const void* p) {
    uint32_t a;
    asm("{ .reg .u64 t; cvta.to.shared.u64 t, %1; cvt.u32.u64 %0, t; }" : "=r"(a) : "l"(p));
    return a;
}
__device__ __forceinline__ void ldsm_x4(uint32_t& r0, uint32_t& r1, uint32_t& r2, uint32_t& r3,
                                        uint32_t addr) {
    asm volatile("ldmatrix.sync.aligned.m8n8.x4.shared.b16 {%0,%1,%2,%3}, [%4];"
                 : "=r"(r0), "=r"(r1), "=r"(r2), "=r"(r3) : "r"(addr));
}
__device__ __forceinline__ void mma_bf16(float* c, uint32_t a0, uint32_t a1, uint32_t a2,
                                         uint32_t a3, uint32_t b0, uint32_t b1) {
    asm volatile(
        "mma.sync.aligned.m16n8k16.row.col.f32.bf16.bf16.f32 "
        "{%0,%1,%2,%3}, {%4,%5,%6,%7}, {%8,%9}, {%0,%1,%2,%3};"
        : "+f"(c[0]), "+f"(c[1]), "+f"(c[2]), "+f"(c[3])
        : "r"(a0), "r"(a1), "r"(a2), "r"(a3), "r"(b0), "r"(b1));
}
#define SWZ(off) ((off) ^ (((off) >> 3) & 0x70))

// ---------------------------------------------------------------- globals
__device__ __align__(16) __nv_bfloat16 g_Bh[BT * FF * NN];  // Wh^T hi (f-major, k=j)
__device__ __align__(16) __nv_bfloat16 g_Bl[BT * FF * NN];  // Wh^T lo
__device__ float g_Eu[BT * NN], g_Fu[BT * NN], g_Ev[BT * NN], g_Fv[BT * NN];
__device__ float g_f1[NN], g_f2[NN];
__device__ unsigned g_adjbits[NN * NN / 32];

// ---------------------------------------------------------------- prep kernels
__global__ void k_f12(const float* __restrict__ emb1, const float* __restrict__ emb2,
                      const float* __restrict__ a2) {
    int i = blockIdx.x * blockDim.x + threadIdx.x;
    if (i < NN) {
        float s1 = 0.f, s2 = 0.f;
#pragma unroll
        for (int m = 0; m < 16; m++) {
            s1 += emb1[i * 16 + m] * a2[m];
            s2 += emb2[i * 16 + m] * a2[16 + m];
        }
        g_f1[i] = s1;
        g_f2[i] = s2;
    }
}

__global__ void k_pack(const int* __restrict__ adj) {
    int gw = (blockIdx.x * blockDim.x + threadIdx.x) >> 5;
    int lane = threadIdx.x & 31;
    int val = adj[(size_t)gw * 32 + lane] > 0;
    unsigned m = __ballot_sync(0xFFFFFFFFu, val);
    if (lane == 0) g_adjbits[gw] = m;
}

// Fused: Wh tile GEMM -> u,v -> Eu/Fu/Ev/Fv -> transposed bf16 hi/lo B operand.
// Block = (j-tile of 64 nodes, bt). g_Wh never touches HBM.
__global__ void __launch_bounds__(256) k_prep(const float* __restrict__ x,
                                              const float* __restrict__ W,
                                              const float* __restrict__ a) {
    __shared__ __align__(16) float Ws[64 * 64];
    __shared__ __align__(16) float ts[64][65];
    __shared__ float sa[128];
    int tid = threadIdx.x;
    int bt = blockIdx.y, j0 = blockIdx.x * 64;

    const float4* W4 = (const float4*)W;
    float4* Ws4 = (float4*)Ws;
#pragma unroll
    for (int k = 0; k < 4; k++) Ws4[tid + 256 * k] = W4[tid + 256 * k];
    if (tid < 128) sa[tid] = a[tid];
#pragma unroll
    for (int kk = 0; kk < 4; kk++) {
        int idx = tid + 256 * kk;
        int r = idx >> 4, c = idx & 15;
        float4 v = *(const float4*)&x[((size_t)(bt * NN) + j0 + r) * 64 + c * 4];
        ts[r][c * 4 + 0] = v.x;
        ts[r][c * 4 + 1] = v.y;
        ts[r][c * 4 + 2] = v.z;
        ts[r][c * 4 + 3] = v.w;
    }
    __syncthreads();

    int f = tid & 63, rb = tid >> 6;
    float acc[16];
#pragma unroll
    for (int r = 0; r < 16; r++) acc[r] = 0.f;
#pragma unroll 4
    for (int k = 0; k < 64; k++) {
        float w = Ws[k * 64 + f];
#pragma unroll
        for (int r = 0; r < 16; r++) acc[r] += ts[rb + 4 * r][k] * w;
    }
    __syncthreads();
#pragma unroll
    for (int r = 0; r < 16; r++) ts[rb + 4 * r][f] = acc[r];
    __syncthreads();

    // u,v per row: 4 threads per row, 16 f each, quad shfl reduce
    {
        int row = tid >> 2, fq = tid & 3;
        float u = 0.f, v = 0.f;
#pragma unroll
        for (int m = 0; m < 16; m++) {
            float wv = ts[row][fq * 16 + m];
            u += wv * sa[fq * 16 + m];
            v += wv * sa[64 + fq * 16 + m];
        }
        u += __shfl_xor_sync(0xFFFFFFFFu, u, 1);
        u += __shfl_xor_sync(0xFFFFFFFFu, u, 2);
        v += __shfl_xor_sync(0xFFFFFFFFu, v, 1);
        v += __shfl_xor_sync(0xFFFFFFFFu, v, 2);
        if (fq == 0) {
            int g = bt * NN + j0 + row;
            float uu = u + g_f1[j0 + row];
            float vv = v + g_f2[j0 + row];
            g_Eu[g] = __expf(uu);
            g_Fu[g] = __expf(0.2f * uu);
            g_Ev[g] = __expf(vv);
            g_Fv[g] = __expf(0.2f * vv);
        }
    }

    // transposed bf16 hi/lo write: B[bt][f][j] = Wh[j][f]
#pragma unroll
    for (int kk = 0; kk < 8; kk++) {
        int pi = tid + 256 * kk;
        int ff = pi >> 5, jp = pi & 31;
        float x0 = ts[2 * jp][ff], x1 = ts[2 * jp + 1][ff];
        __nv_bfloat16 h0 = __float2bfloat16(x0), h1 = __float2bfloat16(x1);
        float l0 = x0 - __bfloat162float(h0), l1 = x1 - __bfloat162float(h1);
        size_t off = ((size_t)(bt * 64 + ff)) * NN + j0 + 2 * jp;
        *(__nv_bfloat162*)&g_Bh[off] = __halves2bfloat162(h0, h1);
        *(__nv_bfloat162*)&g_Bl[off] = __halves2bfloat162(__float2bfloat16(l0), __float2bfloat16(l1));
    }
}

// ---------------------------------------------------------------- main attention kernel
// Double-buffered: build tile t+1 while HMMA consumes tile t. One sync per k-tile.
static constexpr int OFF_AH = 0;       // 128 rows * 128B
static constexpr int OFF_AL = 16384;
static constexpr int OFF_BH = 32768;   // 64 rows * 128B
static constexpr int OFF_BL = 40960;
static constexpr int BUFSZ = 49152;
static constexpr int OFF_EV = 2 * BUFSZ;            // 98304, 1024 f32
static constexpr int OFF_FV = OFF_EV + 4096;
static constexpr int OFF_EU = OFF_FV + 4096;        // 128 f32
static constexpr int OFF_FU = OFF_EU + 512;
static constexpr int OFF_SUM = OFF_FU + 512;
static constexpr int SMEM_DYN = OFF_SUM + 512;      // 108032

__global__ void __launch_bounds__(256, 2) k_att(float* __restrict__ out) {
    extern __shared__ char sm[];
    const uint32_t sb = smem_to_u32(sm);

    const int tid = threadIdx.x;
    const int wid = tid >> 5, lane = tid & 31;
    const int bt = blockIdx.y;
    const int i0 = blockIdx.x * 128;

    float* sEv = (float*)(sm + OFF_EV);
    float* sFv = (float*)(sm + OFF_FV);
    float* sEu = (float*)(sm + OFF_EU);
    float* sFu = (float*)(sm + OFF_FU);
    float* sSum = (float*)(sm + OFF_SUM);
#pragma unroll
    for (int k = 0; k < 4; k++) {
        sEv[tid + 256 * k] = g_Ev[bt * NN + tid + 256 * k];
        sFv[tid + 256 * k] = g_Fv[bt * NN + tid + 256 * k];
    }
    if (tid < 128) {
        sEu[tid] = g_Eu[bt * NN + i0 + tid];
        sFu[tid] = g_Fu[bt * NN + i0 + tid];
    }
    __syncthreads();

    // p-build thread mapping
    const int jq = tid & 15;
    const int rb = tid >> 4;
    float reu[8], rfu[8];
#pragma unroll
    for (int k = 0; k < 8; k++) {
        reu[k] = sEu[rb + 16 * k];
        rfu[k] = sFu[rb + 16 * k];
    }

    // ldmatrix addressing
    const int arow = 16 * wid + (lane & 15);
    const uint32_t aBase = (uint32_t)arow * 128 + ((lane >> 4) << 4);
    const uint32_t aXor = (uint32_t)(arow & 7) << 4;
    const int brl = (lane & 7) | ((lane & 16) >> 1);
    const uint32_t bKoff = (uint32_t)(lane & 8) << 1;

    float acc[8][4];
#pragma unroll
    for (int n = 0; n < 8; n++)
#pragma unroll
        for (int c = 0; c < 4; c++) acc[n][c] = 0.f;
    float rsum[8];
#pragma unroll
    for (int k = 0; k < 8; k++) rsum[k] = 0.f;

#define STAGE_B(T, BASE)                                                              \
    do {                                                                              \
        const int _j0 = (T) * 64;                                                     \
        _Pragma("unroll") for (int rr = 0; rr < 2; rr++) {                            \
            int idx = tid + 256 * rr;                                                 \
            int ff = idx >> 3, q = idx & 7;                                           \
            uint32_t so = SWZ((uint32_t)(ff * 128 + q * 16));                         \
            const uint4* srch = (const uint4*)(g_Bh + ((size_t)(bt * 64 + ff)) * NN + _j0); \
            const uint4* srcl = (const uint4*)(g_Bl + ((size_t)(bt * 64 + ff)) * NN + _j0); \
            *(uint4*)(sm + (BASE) + OFF_BH + so) = srch[q];                           \
            *(uint4*)(sm + (BASE) + OFF_BL + so) = srcl[q];                           \
        }                                                                             \
    } while (0)

#define BUILD_A(T, BASE)                                                              \
    do {                                                                              \
        const int _j0 = (T) * 64;                                                     \
        float4 ev = *(const float4*)(sEv + _j0 + jq * 4);                             \
        float4 fv = *(const float4*)(sFv + _j0 + jq * 4);                             \
        int sh = (jq * 4) & 31;                                                       \
        _Pragma("unroll") for (int k = 0; k < 8; k++) {                               \
            int row = rb + 16 * k;                                                    \
            unsigned word = g_adjbits[(i0 + row) * 32 + ((_j0) >> 5) + (jq >> 3)];    \
            float Eu = reu[k], Fu = rfu[k];                                           \
            float p0 = fmaxf(Eu * ev.x, Fu * fv.x);                                   \
            float p1 = fmaxf(Eu * ev.y, Fu * fv.y);                                   \
            float p2 = fmaxf(Eu * ev.z, Fu * fv.z);                                   \
            float p3 = fmaxf(Eu * ev.w, Fu * fv.w);                                   \
            if (!((word >> (sh + 0)) & 1)) p0 = 0.f;                                  \
            if (!((word >> (sh + 1)) & 1)) p1 = 0.f;                                  \
            if (!((word >> (sh + 2)) & 1)) p2 = 0.f;                                  \
            if (!((word >> (sh + 3)) & 1)) p3 = 0.f;                                  \
            rsum[k] += (p0 + p1) + (p2 + p3);                                         \
            __nv_bfloat16 h0 = __float2bfloat16(p0), h1 = __float2bfloat16(p1);       \
            __nv_bfloat16 h2 = __float2bfloat16(p2), h3 = __float2bfloat16(p3);       \
            float l0 = p0 - __bfloat162float(h0), l1 = p1 - __bfloat162float(h1);     \
            float l2 = p2 - __bfloat162float(h2), l3 = p3 - __bfloat162float(h3);     \
            uint32_t sw = SWZ((uint32_t)(row * 128 + jq * 8));                        \
            __nv_bfloat162 hp0 = __halves2bfloat162(h0, h1);                          \
            __nv_bfloat162 hp1 = __halves2bfloat162(h2, h3);                          \
            uint2 hv = {*reinterpret_cast<uint32_t*>(&hp0), *reinterpret_cast<uint32_t*>(&hp1)}; \
            *(uint2*)(sm + (BASE) + OFF_AH + sw) = hv;                                \
            __nv_bfloat162 lp0 = __halves2bfloat162(__float2bfloat16(l0), __float2bfloat16(l1)); \
            __nv_bfloat162 lp1 = __halves2bfloat162(__float2bfloat16(l2), __float2bfloat16(l3)); \
            uint2 lv = {*reinterpret_cast<uint32_t*>(&lp0), *reinterpret_cast<uint32_t*>(&lp1)}; \
            *(uint2*)(sm + (BASE) + OFF_AL + sw) = lv;                                \
        }                                                                             \
    } while (0)

    // prologue: fill buffer 0
    STAGE_B(0, 0);
    BUILD_A(0, 0);
    __syncthreads();

    for (int t = 0; t < 16; t++) {
        const uint32_t baseCur = (uint32_t)(t & 1) * BUFSZ;
        const uint32_t baseNxt = (uint32_t)((t + 1) & 1) * BUFSZ;
        if (t < 15) {
            STAGE_B(t + 1, baseNxt);
            BUILD_A(t + 1, baseNxt);
        }
        // ---- tensor-core GEMM on current tile
#pragma unroll
        for (int kk = 0; kk < 4; kk++) {
            uint32_t aoff = (aBase + kk * 32) ^ aXor;
            uint32_t ah0, ah1, ah2, ah3, al0, al1, al2, al3;
            ldsm_x4(ah0, ah1, ah2, ah3, sb + baseCur + OFF_AH + aoff);
            ldsm_x4(al0, al1, al2, al3, sb + baseCur + OFF_AL + aoff);
#pragma unroll
            for (int ng = 0; ng < 4; ng++) {
                uint32_t brow = ng * 16 + brl;
                uint32_t boff = (brow * 128 + kk * 32 + bKoff) ^ ((brow & 7) << 4);
                uint32_t bh0, bh1, bh2, bh3, bl0, bl1, bl2, bl3;
                ldsm_x4(bh0, bh1, bh2, bh3, sb + baseCur + OFF_BH + boff);
                ldsm_x4(bl0, bl1, bl2, bl3, sb + baseCur + OFF_BL + boff);
                mma_bf16(acc[2 * ng + 0], ah0, ah1, ah2, ah3, bh0, bh1);
                mma_bf16(acc[2 * ng + 1], ah0, ah1, ah2, ah3, bh2, bh3);
                mma_bf16(acc[2 * ng + 0], ah0, ah1, ah2, ah3, bl0, bl1);
                mma_bf16(acc[2 * ng + 1], ah0, ah1, ah2, ah3, bl2, bl3);
                mma_bf16(acc[2 * ng + 0], al0, al1, al2, al3, bh0, bh1);
                mma_bf16(acc[2 * ng + 1], al0, al1, al2, al3, bh2, bh3);
            }
        }
        __syncthreads();
    }

    // ---- row sums -> smem
#pragma unroll
    for (int k = 0; k < 8; k++) {
        float s = rsum[k];
        s += __shfl_xor_sync(0xFFFFFFFFu, s, 1);
        s += __shfl_xor_sync(0xFFFFFFFFu, s, 2);
        s += __shfl_xor_sync(0xFFFFFFFFu, s, 4);
        s += __shfl_xor_sync(0xFFFFFFFFu, s, 8);
        if (jq == 0) sSum[rb + 16 * k] = s;
    }
    __syncthreads();

    // ---- epilogue: normalize + ELU + store
    {
        int r0 = 16 * wid + (lane >> 2);
        int r1 = r0 + 8;
        float s0 = sSum[r0], s1 = sSum[r1];
        float inv0 = (s0 > 0.f) ? (1.f / s0) : 0.f;
        float inv1 = (s1 > 0.f) ? (1.f / s1) : 0.f;
        float* op0 = out + ((size_t)(bt * NN + i0 + r0)) * 64 + (lane & 3) * 2;
        float* op1 = out + ((size_t)(bt * NN + i0 + r1)) * 64 + (lane & 3) * 2;
#pragma unroll
        for (int nt = 0; nt < 8; nt++) {
            float v0 = acc[nt][0] * inv0, v1 = acc[nt][1] * inv0;
            float v2 = acc[nt][2] * inv1, v3 = acc[nt][3] * inv1;
            float2 o0, o1;
            o0.x = (v0 > 0.f) ? v0 : (__expf(v0) - 1.f);
            o0.y = (v1 > 0.f) ? v1 : (__expf(v1) - 1.f);
            o1.x = (v2 > 0.f) ? v2 : (__expf(v2) - 1.f);
            o1.y = (v3 > 0.f) ? v3 : (__expf(v3) - 1.f);
            *(float2*)(op0 + nt * 8) = o0;
            *(float2*)(op1 + nt * 8) = o1;
        }
    }
}

// ---------------------------------------------------------------- launch
extern "C" void kernel_launch(void* const* d_in, const int* in_sizes, int n_in,
                              void* d_out, int out_size) {
    const float* x = (const float*)d_in[0];
    const int* adj = (const int*)d_in[1];
    const float* emb1 = (const float*)d_in[2];
    const float* emb2 = (const float*)d_in[3];
    const float* W = (const float*)d_in[4];
    const float* a = (const float*)d_in[5];
    const float* a2 = (const float*)d_in[6];
    float* out = (float*)d_out;

    static int smem_set = 0;
    if (!smem_set) {
        cudaFuncSetAttribute(k_att, cudaFuncAttributeMaxDynamicSharedMemorySize, SMEM_DYN);
        smem_set = 1;
    }

    k_f12<<<4, 256>>>(emb1, emb2, a2);
    k_pack<<<NN * NN / 32 / 8, 256>>>(adj);
    dim3 gp(16, BT);
    k_prep<<<gp, 256>>>(x, W, a);
    dim3 ga(8, BT);
    k_att<<<ga, 256, SMEM_DYN>>>(out);
}

// round 5
// speedup vs baseline: 1.3233x; 1.3233x over previous
#include <cuda_runtime.h>
#include <cuda_fp16.h>
#include <cstdint>

#define BT 48
#define NN 1024
#define FF 64

// ---------------------------------------------------------------- helpers
__device__ __forceinline__ uint32_t smem_to_u32(const void* p) {
    uint32_t a;
    asm("{ .reg .u64 t; cvta.to.shared.u64 t, %1; cvt.u32.u64 %0, t; }" : "=r"(a) : "l"(p));
    return a;
}
__device__ __forceinline__ void ldsm_x4(uint32_t& r0, uint32_t& r1, uint32_t& r2, uint32_t& r3,
                                        uint32_t addr) {
    asm volatile("ldmatrix.sync.aligned.m8n8.x4.shared.b16 {%0,%1,%2,%3}, [%4];"
                 : "=r"(r0), "=r"(r1), "=r"(r2), "=r"(r3) : "r"(addr));
}
__device__ __forceinline__ void mma_f16(float* c, uint32_t a0, uint32_t a1, uint32_t a2,
                                        uint32_t a3, uint32_t b0, uint32_t b1) {
    asm volatile(
        "mma.sync.aligned.m16n8k16.row.col.f32.f16.f16.f32 "
        "{%0,%1,%2,%3}, {%4,%5,%6,%7}, {%8,%9}, {%0,%1,%2,%3};"
        : "+f"(c[0]), "+f"(c[1]), "+f"(c[2]), "+f"(c[3])
        : "r"(a0), "r"(a1), "r"(a2), "r"(a3), "r"(b0), "r"(b1));
}
#define SWZ(off) ((off) ^ (((off) >> 3) & 0x70))
#define ONE2 0x3C003C00u  // fp16 {1.0, 1.0}

// ---------------------------------------------------------------- globals
__device__ __align__(16) __half g_Bh[BT * FF * NN];  // Wh^T hi (f-major, k=j)
__device__ __align__(16) __half g_Bl[BT * FF * NN];  // Wh^T lo
__device__ float g_Eu[BT * NN], g_Fu[BT * NN], g_Ev[BT * NN], g_Fv[BT * NN];
__device__ unsigned g_adjbits[NN * NN / 32];

// ---------------------------------------------------------------- prep kernels
__global__ void k_pack(const int* __restrict__ adj) {
    int gw = (blockIdx.x * blockDim.x + threadIdx.x) >> 5;
    int lane = threadIdx.x & 31;
    int val = adj[(size_t)gw * 32 + lane] > 0;
    unsigned m = __ballot_sync(0xFFFFFFFFu, val);
    if (lane == 0) g_adjbits[gw] = m;
}

// Fused: Wh tile GEMM -> u,v (+ emb terms) -> Eu/Fu/Ev/Fv -> transposed fp16 hi/lo B.
__global__ void __launch_bounds__(256) k_prep(const float* __restrict__ x,
                                              const float* __restrict__ W,
                                              const float* __restrict__ a,
                                              const float* __restrict__ emb1,
                                              const float* __restrict__ emb2,
                                              const float* __restrict__ a2) {
    __shared__ __align__(16) float Ws[64 * 64];
    __shared__ __align__(16) float ts[64][65];
    __shared__ float sa[128];
    int tid = threadIdx.x;
    int bt = blockIdx.y, j0 = blockIdx.x * 64;

    const float4* W4 = (const float4*)W;
    float4* Ws4 = (float4*)Ws;
#pragma unroll
    for (int k = 0; k < 4; k++) Ws4[tid + 256 * k] = W4[tid + 256 * k];
    if (tid < 128) sa[tid] = a[tid];
#pragma unroll
    for (int kk = 0; kk < 4; kk++) {
        int idx = tid + 256 * kk;
        int r = idx >> 4, c = idx & 15;
        float4 v = *(const float4*)&x[((size_t)(bt * NN) + j0 + r) * 64 + c * 4];
        ts[r][c * 4 + 0] = v.x;
        ts[r][c * 4 + 1] = v.y;
        ts[r][c * 4 + 2] = v.z;
        ts[r][c * 4 + 3] = v.w;
    }
    __syncthreads();

    int f = tid & 63, rb = tid >> 6;
    float acc[16];
#pragma unroll
    for (int r = 0; r < 16; r++) acc[r] = 0.f;
#pragma unroll 4
    for (int k = 0; k < 64; k++) {
        float w = Ws[k * 64 + f];
#pragma unroll
        for (int r = 0; r < 16; r++) acc[r] += ts[rb + 4 * r][k] * w;
    }
    __syncthreads();
#pragma unroll
    for (int r = 0; r < 16; r++) ts[rb + 4 * r][f] = acc[r];
    __syncthreads();

    // u,v per row: 4 threads per row, 16 f each + 4 emb dims each, quad shfl reduce
    {
        int row = tid >> 2, fq = tid & 3;
        float u = 0.f, v = 0.f;
#pragma unroll
        for (int m = 0; m < 16; m++) {
            float wv = ts[row][fq * 16 + m];
            u += wv * sa[fq * 16 + m];
            v += wv * sa[64 + fq * 16 + m];
        }
#pragma unroll
        for (int m = 0; m < 4; m++) {
            u += emb1[(j0 + row) * 16 + fq * 4 + m] * a2[fq * 4 + m];
            v += emb2[(j0 + row) * 16 + fq * 4 + m] * a2[16 + fq * 4 + m];
        }
        u += __shfl_xor_sync(0xFFFFFFFFu, u, 1);
        u += __shfl_xor_sync(0xFFFFFFFFu, u, 2);
        v += __shfl_xor_sync(0xFFFFFFFFu, v, 1);
        v += __shfl_xor_sync(0xFFFFFFFFu, v, 2);
        if (fq == 0) {
            int g = bt * NN + j0 + row;
            g_Eu[g] = __expf(u);
            g_Fu[g] = __expf(0.2f * u);
            g_Ev[g] = __expf(v);
            g_Fv[g] = __expf(0.2f * v);
        }
    }

    // transposed fp16 hi/lo write: B[bt][f][j] = Wh[j][f]
#pragma unroll
    for (int kk = 0; kk < 8; kk++) {
        int pi = tid + 256 * kk;
        int ff = pi >> 5, jp = pi & 31;
        float x0 = ts[2 * jp][ff], x1 = ts[2 * jp + 1][ff];
        __half h0 = __float2half_rn(x0), h1 = __float2half_rn(x1);
        float l0 = x0 - __half2float(h0), l1 = x1 - __half2float(h1);
        size_t off = ((size_t)(bt * 64 + ff)) * NN + j0 + 2 * jp;
        *(__half2*)&g_Bh[off] = __halves2half2(h0, h1);
        *(__half2*)&g_Bl[off] = __halves2half2(__float2half_rn(l0), __float2half_rn(l1));
    }
}

// ---------------------------------------------------------------- main attention kernel
// A = p tile [128x64] fp16 (single); B = Wh^T [64x64] fp16 hi/lo.
// Row sums via extra MMA against constant all-ones B fragment.
static constexpr int OFF_A = 0;          // 128 rows * 128B = 16384
static constexpr int OFF_BH = 16384;     // 64 rows * 128B = 8192
static constexpr int OFF_BL = 24576;     // 8192
static constexpr int OFF_ADJ = 32768;    // 4096 words = 16384
static constexpr int OFF_EV = 49152;     // 1024 f32
static constexpr int OFF_FV = 53248;
static constexpr int OFF_EU = 57344;     // 128 f32
static constexpr int OFF_FU = 57856;
static constexpr int SMEM_DYN = 58368;

__global__ void __launch_bounds__(256, 3) k_att(float* __restrict__ out) {
    extern __shared__ char sm[];
    const uint32_t sb = smem_to_u32(sm);

    const int tid = threadIdx.x;
    const int wid = tid >> 5, lane = tid & 31;
    const int bt = blockIdx.y;
    const int i0 = blockIdx.x * 128;

    float* sEv = (float*)(sm + OFF_EV);
    float* sFv = (float*)(sm + OFF_FV);
    float* sEu = (float*)(sm + OFF_EU);
    float* sFu = (float*)(sm + OFF_FU);
    unsigned* sAdj = (unsigned*)(sm + OFF_ADJ);
#pragma unroll
    for (int k = 0; k < 4; k++) {
        sEv[tid + 256 * k] = g_Ev[bt * NN + tid + 256 * k];
        sFv[tid + 256 * k] = g_Fv[bt * NN + tid + 256 * k];
    }
    if (tid < 128) {
        sEu[tid] = g_Eu[bt * NN + i0 + tid];
        sFu[tid] = g_Fu[bt * NN + i0 + tid];
    }
    {
        const uint4* gv = (const uint4*)(g_adjbits + (size_t)i0 * 32);
        uint4* sv4 = (uint4*)sAdj;
#pragma unroll
        for (int k = 0; k < 4; k++) sv4[tid + 256 * k] = gv[tid + 256 * k];
    }
    __syncthreads();

    // p-build thread mapping
    const int jq = tid & 15;
    const int rb = tid >> 4;
    const int wcolq = jq >> 3;     // word sub-index (0/1)
    const int sh = (jq * 4) & 31;

    // ldmatrix addressing
    const int arow = 16 * wid + (lane & 15);
    const uint32_t aBase = (uint32_t)arow * 128 + ((lane >> 4) << 4);
    const uint32_t aXor = (uint32_t)(arow & 7) << 4;
    const int brl = (lane & 7) | ((lane & 16) >> 1);
    const uint32_t bKoff = (uint32_t)(lane & 8) << 1;

    float acc[8][4];
#pragma unroll
    for (int n = 0; n < 8; n++)
#pragma unroll
        for (int c = 0; c < 4; c++) acc[n][c] = 0.f;
    float accS[4];
#pragma unroll
    for (int c = 0; c < 4; c++) accS[c] = 0.f;

    for (int t = 0; t < 16; t++) {
        const int j0 = t * 64;
        // ---- stage B hi/lo tiles [64 f x 64 j] fp16, swizzled
#pragma unroll
        for (int rr = 0; rr < 2; rr++) {
            int idx = tid + 256 * rr;
            int ff = idx >> 3, q = idx & 7;
            uint32_t so = SWZ((uint32_t)(ff * 128 + q * 16));
            const uint4* srch = (const uint4*)(g_Bh + ((size_t)(bt * 64 + ff)) * NN + j0);
            const uint4* srcl = (const uint4*)(g_Bl + ((size_t)(bt * 64 + ff)) * NN + j0);
            *(uint4*)(sm + OFF_BH + so) = srch[q];
            *(uint4*)(sm + OFF_BL + so) = srcl[q];
        }
        // ---- build A (p) tile [128 i x 64 j] fp16, swizzled
        {
            float4 ev = *(const float4*)(sEv + j0 + jq * 4);
            float4 fv = *(const float4*)(sFv + j0 + jq * 4);
            const int wcol = (j0 >> 5) + wcolq;
#pragma unroll
            for (int k = 0; k < 8; k++) {
                int row = rb + 16 * k;
                unsigned word = sAdj[row * 32 + wcol];
                float Eu = sEu[row], Fu = sFu[row];
                float p0 = fmaxf(Eu * ev.x, Fu * fv.x);
                float p1 = fmaxf(Eu * ev.y, Fu * fv.y);
                float p2 = fmaxf(Eu * ev.z, Fu * fv.z);
                float p3 = fmaxf(Eu * ev.w, Fu * fv.w);
                if (!((word >> (sh + 0)) & 1)) p0 = 0.f;
                if (!((word >> (sh + 1)) & 1)) p1 = 0.f;
                if (!((word >> (sh + 2)) & 1)) p2 = 0.f;
                if (!((word >> (sh + 3)) & 1)) p3 = 0.f;
                __half2 q0 = __floats2half2_rn(p0, p1);
                __half2 q1 = __floats2half2_rn(p2, p3);
                uint2 hv = {*reinterpret_cast<uint32_t*>(&q0), *reinterpret_cast<uint32_t*>(&q1)};
                *(uint2*)(sm + OFF_A + SWZ((uint32_t)(row * 128 + jq * 8))) = hv;
            }
        }
        __syncthreads();

        // ---- tensor-core GEMM on this k-tile
#pragma unroll
        for (int kk = 0; kk < 4; kk++) {
            uint32_t aoff = (aBase + kk * 32) ^ aXor;
            uint32_t a0, a1, a2r, a3;
            ldsm_x4(a0, a1, a2r, a3, sb + OFF_A + aoff);
            mma_f16(accS, a0, a1, a2r, a3, ONE2, ONE2);  // row sums
#pragma unroll
            for (int ng = 0; ng < 4; ng++) {
                uint32_t brow = ng * 16 + brl;
                uint32_t boff = (brow * 128 + kk * 32 + bKoff) ^ ((brow & 7) << 4);
                uint32_t bh0, bh1, bh2, bh3, bl0, bl1, bl2, bl3;
                ldsm_x4(bh0, bh1, bh2, bh3, sb + OFF_BH + boff);
                ldsm_x4(bl0, bl1, bl2, bl3, sb + OFF_BL + boff);
                mma_f16(acc[2 * ng + 0], a0, a1, a2r, a3, bh0, bh1);
                mma_f16(acc[2 * ng + 1], a0, a1, a2r, a3, bh2, bh3);
                mma_f16(acc[2 * ng + 0], a0, a1, a2r, a3, bl0, bl1);
                mma_f16(acc[2 * ng + 1], a0, a1, a2r, a3, bl2, bl3);
            }
        }
        __syncthreads();
    }

    // ---- epilogue: normalize + ELU + store (row sums already in accS)
    {
        int r0 = 16 * wid + (lane >> 2);
        int r1 = r0 + 8;
        float inv0 = (accS[0] > 0.f) ? (1.f / accS[0]) : 0.f;
        float inv1 = (accS[2] > 0.f) ? (1.f / accS[2]) : 0.f;
        float* op0 = out + ((size_t)(bt * NN + i0 + r0)) * 64 + (lane & 3) * 2;
        float* op1 = out + ((size_t)(bt * NN + i0 + r1)) * 64 + (lane & 3) * 2;
#pragma unroll
        for (int nt = 0; nt < 8; nt++) {
            float v0 = acc[nt][0] * inv0, v1 = acc[nt][1] * inv0;
            float v2 = acc[nt][2] * inv1, v3 = acc[nt][3] * inv1;
            float2 o0, o1;
            o0.x = (v0 > 0.f) ? v0 : (__expf(v0) - 1.f);
            o0.y = (v1 > 0.f) ? v1 : (__expf(v1) - 1.f);
            o1.x = (v2 > 0.f) ? v2 : (__expf(v2) - 1.f);
            o1.y = (v3 > 0.f) ? v3 : (__expf(v3) - 1.f);
            *(float2*)(op0 + nt * 8) = o0;
            *(float2*)(op1 + nt * 8) = o1;
        }
    }
}

// ---------------------------------------------------------------- launch
extern "C" void kernel_launch(void* const* d_in, const int* in_sizes, int n_in,
                              void* d_out, int out_size) {
    const float* x = (const float*)d_in[0];
    const int* adj = (const int*)d_in[1];
    const float* emb1 = (const float*)d_in[2];
    const float* emb2 = (const float*)d_in[3];
    const float* W = (const float*)d_in[4];
    const float* a = (const float*)d_in[5];
    const float* a2 = (const float*)d_in[6];
    float* out = (float*)d_out;

    static int smem_set = 0;
    if (!smem_set) {
        cudaFuncSetAttribute(k_att, cudaFuncAttributeMaxDynamicSharedMemorySize, SMEM_DYN);
        smem_set = 1;
    }

    k_pack<<<NN * NN / 32 / 8, 256>>>(adj);
    dim3 gp(16, BT);
    k_prep<<<gp, 256>>>(x, W, a, emb1, emb2, a2);
    dim3 ga(8, BT);
    k_att<<<ga, 256, SMEM_DYN>>>(out);
}

// round 7
// speedup vs baseline: 1.3844x; 1.0462x over previous
#include <cuda_runtime.h>
#include <cuda_fp16.h>
#include <cstdint>

#define BT 48
#define NN 1024
#define FF 64

// ---------------------------------------------------------------- helpers
__device__ __forceinline__ uint32_t smem_to_u32(const void* p) {
    uint32_t a;
    asm("{ .reg .u64 t; cvta.to.shared.u64 t, %1; cvt.u32.u64 %0, t; }" : "=r"(a) : "l"(p));
    return a;
}
__device__ __forceinline__ void ldsm_x4(uint32_t& r0, uint32_t& r1, uint32_t& r2, uint32_t& r3,
                                        uint32_t addr) {
    asm volatile("ldmatrix.sync.aligned.m8n8.x4.shared.b16 {%0,%1,%2,%3}, [%4];"
                 : "=r"(r0), "=r"(r1), "=r"(r2), "=r"(r3) : "r"(addr));
}
__device__ __forceinline__ void mma_f16(float* c, uint32_t a0, uint32_t a1, uint32_t a2,
                                        uint32_t a3, uint32_t b0, uint32_t b1) {
    asm volatile(
        "mma.sync.aligned.m16n8k16.row.col.f32.f16.f16.f32 "
        "{%0,%1,%2,%3}, {%4,%5,%6,%7}, {%8,%9}, {%0,%1,%2,%3};"
        : "+f"(c[0]), "+f"(c[1]), "+f"(c[2]), "+f"(c[3])
        : "r"(a0), "r"(a1), "r"(a2), "r"(a3), "r"(b0), "r"(b1));
}
#define SWZ(off) ((off) ^ (((off) >> 3) & 0x70))
#define ONE2 0x3C003C00u  // fp16 {1.0, 1.0}

// ---------------------------------------------------------------- globals
__device__ __align__(16) __half g_Bh[BT * FF * NN];  // Wh^T hi (f-major, k=j)
__device__ __align__(16) __half g_Bl[BT * FF * NN];  // Wh^T lo
__device__ __align__(16) __half g_EuH[BT * NN], g_FuH[BT * NN];  // scaled by 0.25
__device__ __align__(16) __half g_EvH[BT * NN], g_FvH[BT * NN];
__device__ unsigned g_adjbits[NN * NN / 32];

// ---------------------------------------------------------------- prep kernels
__global__ void k_pack(const int* __restrict__ adj) {
    int gw = (blockIdx.x * blockDim.x + threadIdx.x) >> 5;
    int lane = threadIdx.x & 31;
    int val = adj[(size_t)gw * 32 + lane] > 0;
    unsigned m = __ballot_sync(0xFFFFFFFFu, val);
    if (lane == 0) g_adjbits[gw] = m;
}

// Fused: Wh tile GEMM -> u,v (+ emb terms) -> exp factors (fp16) -> fp16 hi/lo B.
__global__ void __launch_bounds__(256) k_prep(const float* __restrict__ x,
                                              const float* __restrict__ W,
                                              const float* __restrict__ a,
                                              const float* __restrict__ emb1,
                                              const float* __restrict__ emb2,
                                              const float* __restrict__ a2) {
    __shared__ __align__(16) float Ws[64 * 64];
    __shared__ __align__(16) float ts[64][65];
    __shared__ float sa[128];
    int tid = threadIdx.x;
    int bt = blockIdx.y, j0 = blockIdx.x * 64;

    const float4* W4 = (const float4*)W;
    float4* Ws4 = (float4*)Ws;
#pragma unroll
    for (int k = 0; k < 4; k++) Ws4[tid + 256 * k] = W4[tid + 256 * k];
    if (tid < 128) sa[tid] = a[tid];
#pragma unroll
    for (int kk = 0; kk < 4; kk++) {
        int idx = tid + 256 * kk;
        int r = idx >> 4, c = idx & 15;
        float4 v = *(const float4*)&x[((size_t)(bt * NN) + j0 + r) * 64 + c * 4];
        ts[r][c * 4 + 0] = v.x;
        ts[r][c * 4 + 1] = v.y;
        ts[r][c * 4 + 2] = v.z;
        ts[r][c * 4 + 3] = v.w;
    }
    __syncthreads();

    int f = tid & 63, rb = tid >> 6;
    float acc[16];
#pragma unroll
    for (int r = 0; r < 16; r++) acc[r] = 0.f;
#pragma unroll 4
    for (int k = 0; k < 64; k++) {
        float w = Ws[k * 64 + f];
#pragma unroll
        for (int r = 0; r < 16; r++) acc[r] += ts[rb + 4 * r][k] * w;
    }
    __syncthreads();
#pragma unroll
    for (int r = 0; r < 16; r++) ts[rb + 4 * r][f] = acc[r];
    __syncthreads();

    // u,v per row: 4 threads per row, quad shfl reduce
    {
        int row = tid >> 2, fq = tid & 3;
        float u = 0.f, v = 0.f;
#pragma unroll
        for (int m = 0; m < 16; m++) {
            float wv = ts[row][fq * 16 + m];
            u += wv * sa[fq * 16 + m];
            v += wv * sa[64 + fq * 16 + m];
        }
#pragma unroll
        for (int m = 0; m < 4; m++) {
            u += emb1[(j0 + row) * 16 + fq * 4 + m] * a2[fq * 4 + m];
            v += emb2[(j0 + row) * 16 + fq * 4 + m] * a2[16 + fq * 4 + m];
        }
        u += __shfl_xor_sync(0xFFFFFFFFu, u, 1);
        u += __shfl_xor_sync(0xFFFFFFFFu, u, 2);
        v += __shfl_xor_sync(0xFFFFFFFFu, v, 1);
        v += __shfl_xor_sync(0xFFFFFFFFu, v, 2);
        if (fq == 0) {
            int g = bt * NN + j0 + row;
            g_EuH[g] = __float2half_rn(__expf(u) * 0.25f);
            g_FuH[g] = __float2half_rn(__expf(0.2f * u) * 0.25f);
            g_EvH[g] = __float2half_rn(__expf(v));
            g_FvH[g] = __float2half_rn(__expf(0.2f * v));
        }
    }

    // transposed fp16 hi/lo write: B[bt][f][j] = Wh[j][f]
#pragma unroll
    for (int kk = 0; kk < 8; kk++) {
        int pi = tid + 256 * kk;
        int ff = pi >> 5, jp = pi & 31;
        float x0 = ts[2 * jp][ff], x1 = ts[2 * jp + 1][ff];
        __half h0 = __float2half_rn(x0), h1 = __float2half_rn(x1);
        float l0 = x0 - __half2float(h0), l1 = x1 - __half2float(h1);
        size_t off = ((size_t)(bt * 64 + ff)) * NN + j0 + 2 * jp;
        *(__half2*)&g_Bh[off] = __halves2half2(h0, h1);
        *(__half2*)&g_Bl[off] = __halves2half2(__float2half_rn(l0), __float2half_rn(l1));
    }
}

// ---------------------------------------------------------------- main attention kernel
// A = p tile [128x64] fp16 (half2 build); B = Wh^T [64x64] fp16 hi/lo.
// Warp tile 32M x 32N. Row sums via MMA against all-ones fragment.
static constexpr int OFF_A = 0;          // 128 rows * 128B = 16384
static constexpr int OFF_BH = 16384;     // 8192
static constexpr int OFF_BL = 24576;     // 8192
static constexpr int OFF_ADJ = 32768;    // 4096 words = 16384
static constexpr int OFF_EV = 49152;     // 1024 half = 2048
static constexpr int OFF_FV = 51200;     // 2048
static constexpr int OFF_EU = 53248;     // 128 half = 256
static constexpr int OFF_FU = 53504;     // 256
static constexpr int OFF_LUT = 53760;    // 16 * uint2 = 128
static constexpr int SMEM_DYN = 53888;

__global__ void __launch_bounds__(256, 3) k_att(float* __restrict__ out) {
    extern __shared__ char sm[];
    const uint32_t sb = smem_to_u32(sm);

    const int tid = threadIdx.x;
    const int wid = tid >> 5, lane = tid & 31;
    const int bt = blockIdx.y;
    const int i0 = blockIdx.x * 128;

    __half* sEvH = (__half*)(sm + OFF_EV);
    __half* sFvH = (__half*)(sm + OFF_FV);
    __half* sEuH = (__half*)(sm + OFF_EU);
    __half* sFuH = (__half*)(sm + OFF_FU);
    unsigned* sAdj = (unsigned*)(sm + OFF_ADJ);
    uint2* sLut = (uint2*)(sm + OFF_LUT);

    // stage Ev/Fv (2KB each), Eu/Fu (256B each), adj slice (16KB), LUT
    if (tid < 128) {
        ((uint4*)sEvH)[tid] = ((const uint4*)(g_EvH + bt * NN))[tid];
        ((uint4*)sFvH)[tid] = ((const uint4*)(g_FvH + bt * NN))[tid];
    } else if (tid < 144) {
        ((uint4*)sEuH)[tid - 128] = ((const uint4*)(g_EuH + bt * NN + i0))[tid - 128];
        ((uint4*)sFuH)[tid - 128] = ((const uint4*)(g_FuH + bt * NN + i0))[tid - 128];
    } else if (tid < 160) {
        int n = tid - 144;
        uint2 m;
        m.x = ((n & 1) ? 0xFFFFu : 0u) | ((n & 2) ? 0xFFFF0000u : 0u);
        m.y = ((n & 4) ? 0xFFFFu : 0u) | ((n & 8) ? 0xFFFF0000u : 0u);
        sLut[n] = m;
    }
    {
        const uint4* gv = (const uint4*)(g_adjbits + (size_t)i0 * 32);
        uint4* sv4 = (uint4*)sAdj;
#pragma unroll
        for (int k = 0; k < 4; k++) sv4[tid + 256 * k] = gv[tid + 256 * k];
    }
    __syncthreads();

    // p-build thread mapping: row group rb (+16k), j-quad jq
    const int jq = tid & 15;
    const int rb = tid >> 4;
    const int wcolq = jq >> 3;
    const int sh = (jq * 4) & 31;
    __half2 Eu2[8], Fu2[8];
#pragma unroll
    for (int k = 0; k < 8; k++) {
        Eu2[k] = __half2half2(sEuH[rb + 16 * k]);
        Fu2[k] = __half2half2(sFuH[rb + 16 * k]);
    }

    // ldmatrix addressing: warp tile 32M x 32N
    const int mg = wid >> 1;        // 0..3  (rows 32mg..+31)
    const int ngrp = wid & 1;       // 0..1  (cols 32ngrp..+31)
    const int arow0 = 32 * mg + (lane & 15);
    const uint32_t aBase0 = (uint32_t)arow0 * 128 + ((lane >> 4) << 4);
    const uint32_t aXor = (uint32_t)(arow0 & 7) << 4;
    const int brl = (lane & 7) | ((lane & 16) >> 1);
    const uint32_t bKoff = (uint32_t)(lane & 8) << 1;
    const uint32_t brow0 = 32 * ngrp + brl;          // bg=0 base row
    const uint32_t bXor = (brow0 & 7) << 4;

    float acc[2][4][4];
#pragma unroll
    for (int m = 0; m < 2; m++)
#pragma unroll
        for (int g = 0; g < 4; g++)
#pragma unroll
            for (int c = 0; c < 4; c++) acc[m][g][c] = 0.f;
    float accS[2][4];
#pragma unroll
    for (int m = 0; m < 2; m++)
#pragma unroll
        for (int c = 0; c < 4; c++) accS[m][c] = 0.f;

    for (int t = 0; t < 16; t++) {
        const int j0 = t * 64;
        // ---- stage B hi/lo tiles [64 f x 64 j] fp16, swizzled
#pragma unroll
        for (int rr = 0; rr < 2; rr++) {
            int idx = tid + 256 * rr;
            int ff = idx >> 3, q = idx & 7;
            uint32_t so = SWZ((uint32_t)(ff * 128 + q * 16));
            const uint4* srch = (const uint4*)(g_Bh + ((size_t)(bt * 64 + ff)) * NN + j0);
            const uint4* srcl = (const uint4*)(g_Bl + ((size_t)(bt * 64 + ff)) * NN + j0);
            *(uint4*)(sm + OFF_BH + so) = srch[q];
            *(uint4*)(sm + OFF_BL + so) = srcl[q];
        }
        // ---- build A (p) tile [128 i x 64 j] fp16, half2 path
        {
            __half2 ev0 = *(const __half2*)(sEvH + j0 + jq * 4);
            __half2 ev1 = *(const __half2*)(sEvH + j0 + jq * 4 + 2);
            __half2 fv0 = *(const __half2*)(sFvH + j0 + jq * 4);
            __half2 fv1 = *(const __half2*)(sFvH + j0 + jq * 4 + 2);
            const int wcol = (j0 >> 5) + wcolq;
#pragma unroll
            for (int k = 0; k < 8; k++) {
                int row = rb + 16 * k;
                unsigned word = sAdj[row * 32 + wcol];
                uint2 msk = sLut[(word >> sh) & 15];
                __half2 p0 = __hmax2(__hmul2(Eu2[k], ev0), __hmul2(Fu2[k], fv0));
                __half2 p1 = __hmax2(__hmul2(Eu2[k], ev1), __hmul2(Fu2[k], fv1));
                uint2 hv;
                hv.x = *reinterpret_cast<uint32_t*>(&p0) & msk.x;
                hv.y = *reinterpret_cast<uint32_t*>(&p1) & msk.y;
                *(uint2*)(sm + OFF_A + SWZ((uint32_t)(row * 128 + jq * 8))) = hv;
            }
        }
        __syncthreads();

        // ---- tensor-core GEMM on this k-tile
#pragma unroll
        for (int kk = 0; kk < 4; kk++) {
            uint32_t a00, a01, a02, a03, a10, a11, a12, a13;
            uint32_t ao = (aBase0 + kk * 32) ^ aXor;
            ldsm_x4(a00, a01, a02, a03, sb + OFF_A + ao);
            ldsm_x4(a10, a11, a12, a13, sb + OFF_A + (ao + 2048));
            mma_f16(accS[0], a00, a01, a02, a03, ONE2, ONE2);
            mma_f16(accS[1], a10, a11, a12, a13, ONE2, ONE2);
#pragma unroll
            for (int bg = 0; bg < 2; bg++) {
                uint32_t bo = ((brow0 + 16 * bg) * 128 + kk * 32 + bKoff) ^ bXor;
                uint32_t bh0, bh1, bh2, bh3, bl0, bl1, bl2, bl3;
                ldsm_x4(bh0, bh1, bh2, bh3, sb + OFF_BH + bo);
                ldsm_x4(bl0, bl1, bl2, bl3, sb + OFF_BL + bo);
                mma_f16(acc[0][2 * bg + 0], a00, a01, a02, a03, bh0, bh1);
                mma_f16(acc[0][2 * bg + 1], a00, a01, a02, a03, bh2, bh3);
                mma_f16(acc[1][2 * bg + 0], a10, a11, a12, a13, bh0, bh1);
                mma_f16(acc[1][2 * bg + 1], a10, a11, a12, a13, bh2, bh3);
                mma_f16(acc[0][2 * bg + 0], a00, a01, a02, a03, bl0, bl1);
                mma_f16(acc[0][2 * bg + 1], a00, a01, a02, a03, bl2, bl3);
                mma_f16(acc[1][2 * bg + 0], a10, a11, a12, a13, bl0, bl1);
                mma_f16(acc[1][2 * bg + 1], a10, a11, a12, a13, bl2, bl3);
            }
        }
        __syncthreads();
    }

    // ---- epilogue: normalize + ELU + store
#pragma unroll
    for (int m = 0; m < 2; m++) {
        int r0 = i0 + 32 * mg + 16 * m + (lane >> 2);
        float inv0 = (accS[m][0] > 0.f) ? (1.f / accS[m][0]) : 0.f;
        float inv1 = (accS[m][2] > 0.f) ? (1.f / accS[m][2]) : 0.f;
        float* op0 = out + ((size_t)(bt * NN + r0)) * 64;
        float* op1 = op0 + (size_t)8 * 64;
#pragma unroll
        for (int bg = 0; bg < 2; bg++)
#pragma unroll
            for (int h = 0; h < 2; h++) {
                int colb = 32 * ngrp + 16 * bg + 8 * h + (lane & 3) * 2;
                const float* A = acc[m][2 * bg + h];
                float v0 = A[0] * inv0, v1 = A[1] * inv0;
                float v2 = A[2] * inv1, v3 = A[3] * inv1;
                float2 o0, o1;
                o0.x = (v0 > 0.f) ? v0 : (__expf(v0) - 1.f);
                o0.y = (v1 > 0.f) ? v1 : (__expf(v1) - 1.f);
                o1.x = (v2 > 0.f) ? v2 : (__expf(v2) - 1.f);
                o1.y = (v3 > 0.f) ? v3 : (__expf(v3) - 1.f);
                *(float2*)(op0 + colb) = o0;
                *(float2*)(op1 + colb) = o1;
            }
    }
}

// ---------------------------------------------------------------- launch
extern "C" void kernel_launch(void* const* d_in, const int* in_sizes, int n_in,
                              void* d_out, int out_size) {
    const float* x = (const float*)d_in[0];
    const int* adj = (const int*)d_in[1];
    const float* emb1 = (const float*)d_in[2];
    const float* emb2 = (const float*)d_in[3];
    const float* W = (const float*)d_in[4];
    const float* a = (const float*)d_in[5];
    const float* a2 = (const float*)d_in[6];
    float* out = (float*)d_out;

    static int smem_set = 0;
    if (!smem_set) {
        cudaFuncSetAttribute(k_att, cudaFuncAttributeMaxDynamicSharedMemorySize, SMEM_DYN);
        smem_set = 1;
    }

    k_pack<<<NN * NN / 32 / 8, 256>>>(adj);
    dim3 gp(16, BT);
    k_prep<<<gp, 256>>>(x, W, a, emb1, emb2, a2);
    dim3 ga(8, BT);
    k_att<<<ga, 256, SMEM_DYN>>>(out);
}

// round 8
// speedup vs baseline: 1.6271x; 1.1753x over previous
#include <cuda_runtime.h>
#include <cuda_fp16.h>
#include <cstdint>

#define BT 48
#define NN 1024
#define FF 64

// ---------------------------------------------------------------- helpers
__device__ __forceinline__ uint32_t smem_to_u32(const void* p) {
    uint32_t a;
    asm("{ .reg .u64 t; cvta.to.shared.u64 t, %1; cvt.u32.u64 %0, t; }" : "=r"(a) : "l"(p));
    return a;
}
__device__ __forceinline__ void ldsm_x4(uint32_t& r0, uint32_t& r1, uint32_t& r2, uint32_t& r3,
                                        uint32_t addr) {
    asm volatile("ldmatrix.sync.aligned.m8n8.x4.shared.b16 {%0,%1,%2,%3}, [%4];"
                 : "=r"(r0), "=r"(r1), "=r"(r2), "=r"(r3) : "r"(addr));
}
__device__ __forceinline__ void mma_f16(float* c, uint32_t a0, uint32_t a1, uint32_t a2,
                                        uint32_t a3, uint32_t b0, uint32_t b1) {
    asm volatile(
        "mma.sync.aligned.m16n8k16.row.col.f32.f16.f16.f32 "
        "{%0,%1,%2,%3}, {%4,%5,%6,%7}, {%8,%9}, {%0,%1,%2,%3};"
        : "+f"(c[0]), "+f"(c[1]), "+f"(c[2]), "+f"(c[3])
        : "r"(a0), "r"(a1), "r"(a2), "r"(a3), "r"(b0), "r"(b1));
}
#define SWZ(off) ((off) ^ (((off) >> 3) & 0x70))
#define ONE2 0x3C003C00u  // fp16 {1.0, 1.0}

// ---------------------------------------------------------------- globals
__device__ __align__(16) __half g_B[BT * FF * NN];   // Wh^T fp16 (f-major, k=j)
__device__ __align__(16) __half g_EuH[BT * NN], g_FuH[BT * NN];  // scaled by 0.25
__device__ __align__(16) __half g_EvH[BT * NN], g_FvH[BT * NN];
__device__ unsigned g_adjbits[NN * NN / 32];

// ---------------------------------------------------------------- prep kernels
// Vectorized pack: each thread loads 4 ints; 8-lane groups assemble one 32-bit word.
__global__ void k_pack(const int* __restrict__ adj) {
    int gid = blockIdx.x * blockDim.x + threadIdx.x;   // 262144 threads
    int lane = threadIdx.x & 31;
    uint4 v = ((const uint4*)adj)[gid];
    unsigned nib = (v.x ? 1u : 0u) | (v.y ? 2u : 0u) | (v.z ? 4u : 0u) | (v.w ? 8u : 0u);
    unsigned grp = lane >> 3;                  // 0..3
    unsigned mask = 0xFFu << (8 * grp);
    unsigned word = __reduce_or_sync(mask, nib << (4 * (lane & 7)));
    if ((lane & 7) == 0) g_adjbits[gid >> 3] = word;
}

// Fused: Wh tile GEMM -> u,v (+ emb terms) -> exp factors (fp16) -> fp16 B.
__global__ void __launch_bounds__(256) k_prep(const float* __restrict__ x,
                                              const float* __restrict__ W,
                                              const float* __restrict__ a,
                                              const float* __restrict__ emb1,
                                              const float* __restrict__ emb2,
                                              const float* __restrict__ a2) {
    __shared__ __align__(16) float Ws[64 * 64];
    __shared__ __align__(16) float ts[64][65];
    __shared__ float sa[128];
    int tid = threadIdx.x;
    int bt = blockIdx.y, j0 = blockIdx.x * 64;

    const float4* W4 = (const float4*)W;
    float4* Ws4 = (float4*)Ws;
#pragma unroll
    for (int k = 0; k < 4; k++) Ws4[tid + 256 * k] = W4[tid + 256 * k];
    if (tid < 128) sa[tid] = a[tid];
#pragma unroll
    for (int kk = 0; kk < 4; kk++) {
        int idx = tid + 256 * kk;
        int r = idx >> 4, c = idx & 15;
        float4 v = *(const float4*)&x[((size_t)(bt * NN) + j0 + r) * 64 + c * 4];
        ts[r][c * 4 + 0] = v.x;
        ts[r][c * 4 + 1] = v.y;
        ts[r][c * 4 + 2] = v.z;
        ts[r][c * 4 + 3] = v.w;
    }
    __syncthreads();

    int f = tid & 63, rb = tid >> 6;
    float acc[16];
#pragma unroll
    for (int r = 0; r < 16; r++) acc[r] = 0.f;
#pragma unroll 4
    for (int k = 0; k < 64; k++) {
        float w = Ws[k * 64 + f];
#pragma unroll
        for (int r = 0; r < 16; r++) acc[r] += ts[rb + 4 * r][k] * w;
    }
    __syncthreads();
#pragma unroll
    for (int r = 0; r < 16; r++) ts[rb + 4 * r][f] = acc[r];
    __syncthreads();

    // u,v per row: 4 threads per row, quad shfl reduce
    {
        int row = tid >> 2, fq = tid & 3;
        float u = 0.f, v = 0.f;
#pragma unroll
        for (int m = 0; m < 16; m++) {
            float wv = ts[row][fq * 16 + m];
            u += wv * sa[fq * 16 + m];
            v += wv * sa[64 + fq * 16 + m];
        }
#pragma unroll
        for (int m = 0; m < 4; m++) {
            u += emb1[(j0 + row) * 16 + fq * 4 + m] * a2[fq * 4 + m];
            v += emb2[(j0 + row) * 16 + fq * 4 + m] * a2[16 + fq * 4 + m];
        }
        u += __shfl_xor_sync(0xFFFFFFFFu, u, 1);
        u += __shfl_xor_sync(0xFFFFFFFFu, u, 2);
        v += __shfl_xor_sync(0xFFFFFFFFu, v, 1);
        v += __shfl_xor_sync(0xFFFFFFFFu, v, 2);
        if (fq == 0) {
            int g = bt * NN + j0 + row;
            g_EuH[g] = __float2half_rn(__expf(u) * 0.25f);
            g_FuH[g] = __float2half_rn(__expf(0.2f * u) * 0.25f);
            g_EvH[g] = __float2half_rn(__expf(v));
            g_FvH[g] = __float2half_rn(__expf(0.2f * v));
        }
    }

    // transposed fp16 write: B[bt][f][j] = Wh[j][f]
#pragma unroll
    for (int kk = 0; kk < 8; kk++) {
        int pi = tid + 256 * kk;
        int ff = pi >> 5, jp = pi & 31;
        float x0 = ts[2 * jp][ff], x1 = ts[2 * jp + 1][ff];
        size_t off = ((size_t)(bt * 64 + ff)) * NN + j0 + 2 * jp;
        *(__half2*)&g_B[off] = __floats2half2_rn(x0, x1);
    }
}

// ---------------------------------------------------------------- main attention kernel
// A = p tile [128x64] fp16 (half2 build); B = Wh^T [64x64] fp16 single.
// Warp tile 32M x 32N. Row sums via MMA against all-ones fragment.
static constexpr int OFF_A = 0;          // 16384
static constexpr int OFF_B = 16384;      // 8192
static constexpr int OFF_ADJ = 24576;    // 16384
static constexpr int OFF_EV = 40960;     // 2048
static constexpr int OFF_FV = 43008;     // 2048
static constexpr int OFF_EU = 45056;     // 256
static constexpr int OFF_FU = 45312;     // 256
static constexpr int OFF_LUT = 45568;    // 128
static constexpr int SMEM_DYN = 45696;

__global__ void __launch_bounds__(256, 3) k_att(float* __restrict__ out) {
    extern __shared__ char sm[];
    const uint32_t sb = smem_to_u32(sm);

    const int tid = threadIdx.x;
    const int wid = tid >> 5, lane = tid & 31;
    const int bt = blockIdx.y;
    const int i0 = blockIdx.x * 128;

    __half* sEvH = (__half*)(sm + OFF_EV);
    __half* sFvH = (__half*)(sm + OFF_FV);
    __half* sEuH = (__half*)(sm + OFF_EU);
    __half* sFuH = (__half*)(sm + OFF_FU);
    unsigned* sAdj = (unsigned*)(sm + OFF_ADJ);
    uint2* sLut = (uint2*)(sm + OFF_LUT);

    if (tid < 128) {
        ((uint4*)sEvH)[tid] = ((const uint4*)(g_EvH + bt * NN))[tid];
        ((uint4*)sFvH)[tid] = ((const uint4*)(g_FvH + bt * NN))[tid];
    } else if (tid < 144) {
        ((uint4*)sEuH)[tid - 128] = ((const uint4*)(g_EuH + bt * NN + i0))[tid - 128];
        ((uint4*)sFuH)[tid - 128] = ((const uint4*)(g_FuH + bt * NN + i0))[tid - 128];
    } else if (tid < 160) {
        int n = tid - 144;
        uint2 m;
        m.x = ((n & 1) ? 0xFFFFu : 0u) | ((n & 2) ? 0xFFFF0000u : 0u);
        m.y = ((n & 4) ? 0xFFFFu : 0u) | ((n & 8) ? 0xFFFF0000u : 0u);
        sLut[n] = m;
    }
    {
        const uint4* gv = (const uint4*)(g_adjbits + (size_t)i0 * 32);
        uint4* sv4 = (uint4*)sAdj;
#pragma unroll
        for (int k = 0; k < 4; k++) sv4[tid + 256 * k] = gv[tid + 256 * k];
    }
    __syncthreads();

    // p-build thread mapping
    const int jq = tid & 15;
    const int rb = tid >> 4;
    const int wcolq = jq >> 3;
    const int sh = (jq * 4) & 31;
    __half2 Eu2[8], Fu2[8];
#pragma unroll
    for (int k = 0; k < 8; k++) {
        Eu2[k] = __half2half2(sEuH[rb + 16 * k]);
        Fu2[k] = __half2half2(sFuH[rb + 16 * k]);
    }

    // ldmatrix addressing: warp tile 32M x 32N
    const int mg = wid >> 1;
    const int ngrp = wid & 1;
    const int arow0 = 32 * mg + (lane & 15);
    const uint32_t aBase0 = (uint32_t)arow0 * 128 + ((lane >> 4) << 4);
    const uint32_t aXor = (uint32_t)(arow0 & 7) << 4;
    const int brl = (lane & 7) | ((lane & 16) >> 1);
    const uint32_t bKoff = (uint32_t)(lane & 8) << 1;
    const uint32_t brow0 = 32 * ngrp + brl;
    const uint32_t bXor = (brow0 & 7) << 4;

    float acc[2][4][4];
#pragma unroll
    for (int m = 0; m < 2; m++)
#pragma unroll
        for (int g = 0; g < 4; g++)
#pragma unroll
            for (int c = 0; c < 4; c++) acc[m][g][c] = 0.f;
    float accS[2][4];
#pragma unroll
    for (int m = 0; m < 2; m++)
#pragma unroll
        for (int c = 0; c < 4; c++) accS[m][c] = 0.f;

    for (int t = 0; t < 16; t++) {
        const int j0 = t * 64;
        // ---- stage B tile [64 f x 64 j] fp16, swizzled
#pragma unroll
        for (int rr = 0; rr < 2; rr++) {
            int idx = tid + 256 * rr;
            int ff = idx >> 3, q = idx & 7;
            uint32_t so = SWZ((uint32_t)(ff * 128 + q * 16));
            const uint4* srcb = (const uint4*)(g_B + ((size_t)(bt * 64 + ff)) * NN + j0);
            *(uint4*)(sm + OFF_B + so) = srcb[q];
        }
        // ---- build A (p) tile [128 i x 64 j] fp16, half2 path
        {
            __half2 ev0 = *(const __half2*)(sEvH + j0 + jq * 4);
            __half2 ev1 = *(const __half2*)(sEvH + j0 + jq * 4 + 2);
            __half2 fv0 = *(const __half2*)(sFvH + j0 + jq * 4);
            __half2 fv1 = *(const __half2*)(sFvH + j0 + jq * 4 + 2);
            const int wcol = (j0 >> 5) + wcolq;
#pragma unroll
            for (int k = 0; k < 8; k++) {
                int row = rb + 16 * k;
                unsigned word = sAdj[row * 32 + wcol];
                uint2 msk = sLut[(word >> sh) & 15];
                __half2 p0 = __hmax2(__hmul2(Eu2[k], ev0), __hmul2(Fu2[k], fv0));
                __half2 p1 = __hmax2(__hmul2(Eu2[k], ev1), __hmul2(Fu2[k], fv1));
                uint2 hv;
                hv.x = *reinterpret_cast<uint32_t*>(&p0) & msk.x;
                hv.y = *reinterpret_cast<uint32_t*>(&p1) & msk.y;
                *(uint2*)(sm + OFF_A + SWZ((uint32_t)(row * 128 + jq * 8))) = hv;
            }
        }
        __syncthreads();

        // ---- tensor-core GEMM on this k-tile
#pragma unroll
        for (int kk = 0; kk < 4; kk++) {
            uint32_t a00, a01, a02, a03, a10, a11, a12, a13;
            uint32_t ao = (aBase0 + kk * 32) ^ aXor;
            ldsm_x4(a00, a01, a02, a03, sb + OFF_A + ao);
            ldsm_x4(a10, a11, a12, a13, sb + OFF_A + (ao + 2048));
            mma_f16(accS[0], a00, a01, a02, a03, ONE2, ONE2);
            mma_f16(accS[1], a10, a11, a12, a13, ONE2, ONE2);
#pragma unroll
            for (int bg = 0; bg < 2; bg++) {
                uint32_t bo = ((brow0 + 16 * bg) * 128 + kk * 32 + bKoff) ^ bXor;
                uint32_t b0, b1, b2, b3;
                ldsm_x4(b0, b1, b2, b3, sb + OFF_B + bo);
                mma_f16(acc[0][2 * bg + 0], a00, a01, a02, a03, b0, b1);
                mma_f16(acc[0][2 * bg + 1], a00, a01, a02, a03, b2, b3);
                mma_f16(acc[1][2 * bg + 0], a10, a11, a12, a13, b0, b1);
                mma_f16(acc[1][2 * bg + 1], a10, a11, a12, a13, b2, b3);
            }
        }
        __syncthreads();
    }

    // ---- epilogue: normalize + ELU + store
#pragma unroll
    for (int m = 0; m < 2; m++) {
        int r0 = i0 + 32 * mg + 16 * m + (lane >> 2);
        float inv0 = (accS[m][0] > 0.f) ? (1.f / accS[m][0]) : 0.f;
        float inv1 = (accS[m][2] > 0.f) ? (1.f / accS[m][2]) : 0.f;
        float* op0 = out + ((size_t)(bt * NN + r0)) * 64;
        float* op1 = op0 + (size_t)8 * 64;
#pragma unroll
        for (int bg = 0; bg < 2; bg++)
#pragma unroll
            for (int h = 0; h < 2; h++) {
                int colb = 32 * ngrp + 16 * bg + 8 * h + (lane & 3) * 2;
                const float* A = acc[m][2 * bg + h];
                float v0 = A[0] * inv0, v1 = A[1] * inv0;
                float v2 = A[2] * inv1, v3 = A[3] * inv1;
                float2 o0, o1;
                o0.x = (v0 > 0.f) ? v0 : (__expf(v0) - 1.f);
                o0.y = (v1 > 0.f) ? v1 : (__expf(v1) - 1.f);
                o1.x = (v2 > 0.f) ? v2 : (__expf(v2) - 1.f);
                o1.y = (v3 > 0.f) ? v3 : (__expf(v3) - 1.f);
                *(float2*)(op0 + colb) = o0;
                *(float2*)(op1 + colb) = o1;
            }
    }
}

// ---------------------------------------------------------------- launch
extern "C" void kernel_launch(void* const* d_in, const int* in_sizes, int n_in,
                              void* d_out, int out_size) {
    const float* x = (const float*)d_in[0];
    const int* adj = (const int*)d_in[1];
    const float* emb1 = (const float*)d_in[2];
    const float* emb2 = (const float*)d_in[3];
    const float* W = (const float*)d_in[4];
    const float* a = (const float*)d_in[5];
    const float* a2 = (const float*)d_in[6];
    float* out = (float*)d_out;

    static int smem_set = 0;
    if (!smem_set) {
        cudaFuncSetAttribute(k_att, cudaFuncAttributeMaxDynamicSharedMemorySize, SMEM_DYN);
        smem_set = 1;
    }

    k_pack<<<1024, 256>>>(adj);
    dim3 gp(16, BT);
    k_prep<<<gp, 256>>>(x, W, a, emb1, emb2, a2);
    dim3 ga(8, BT);
    k_att<<<ga, 256, SMEM_DYN>>>(out);
}